// round 8
// baseline (speedup 1.0000x reference)
#include <cuda_runtime.h>
#include <cuda_bf16.h>
#include <cstdint>

// NetVLAD: B=64, C=128, K=64, N=4096 — mma.sync bf16 3-term split
// R8: M=32 per warp + k-split across warps in both GEMMs (-20% ldmatrix traffic).
#define NV_B 64
#define NV_C 128
#define NV_K 64
#define NV_N 4096
#define NV_SPLIT 8
#define NV_TILES 8           // tiles of n=64

// smem pitches (bf16 elements)
#define PX 72       // Xn rows (c): 64 + 8 pad
#define PW 136      // W rows (k): 128 + 8 pad
#define PA 72       // At rows (n): 64 + 8 pad

// smem byte offsets
#define XN_HI 0
#define XN_LO (XN_HI + 128 * PX * 2)      // 18432
#define W_HI  (XN_LO + 128 * PX * 2)      // 36864
#define W_LO  (W_HI + 64 * PW * 2)        // 54272
#define AT_HI (W_LO + 64 * PW * 2)        // 71680
#define AT_LO (AT_HI + 64 * PA * 2)       // 80896
#define AUX_B (AT_LO + 64 * PA * 2)       // 90112 : stats (1KB) then asum buf
#define SMEM_TOTAL (AUX_B + 1024)         // 91136

// scratch partials
__device__ float g_pvlad[(size_t)NV_B * NV_SPLIT * NV_K * NV_C];  // 16 MB
__device__ float g_pasum[NV_B * NV_SPLIT * NV_K];

__device__ __forceinline__ uint32_t smem_u32(const void* p) {
    uint32_t a;
    asm("{ .reg .u64 t; cvta.to.shared.u64 t, %1; cvt.u32.u64 %0, t; }" : "=r"(a) : "l"(p));
    return a;
}
__device__ __forceinline__ void ldmx4(uint32_t* r, uint32_t a) {
    asm volatile("ldmatrix.sync.aligned.m8n8.x4.shared.b16 {%0,%1,%2,%3},[%4];"
        : "=r"(r[0]), "=r"(r[1]), "=r"(r[2]), "=r"(r[3]) : "r"(a));
}
__device__ __forceinline__ void ldmx4t(uint32_t* r, uint32_t a) {
    asm volatile("ldmatrix.sync.aligned.m8n8.x4.trans.shared.b16 {%0,%1,%2,%3},[%4];"
        : "=r"(r[0]), "=r"(r[1]), "=r"(r[2]), "=r"(r[3]) : "r"(a));
}
__device__ __forceinline__ void mma16816(float* d, const uint32_t* a, const uint32_t* b) {
    asm volatile("mma.sync.aligned.m16n8k16.row.col.f32.bf16.bf16.f32 "
        "{%0,%1,%2,%3},{%4,%5,%6,%7},{%8,%9},{%0,%1,%2,%3};"
        : "+f"(d[0]), "+f"(d[1]), "+f"(d[2]), "+f"(d[3])
        : "r"(a[0]), "r"(a[1]), "r"(a[2]), "r"(a[3]), "r"(b[0]), "r"(b[1]));
}

// ---------------------------------------------------------------------------
__global__ __launch_bounds__(256, 2)
void netvlad_mma(const float* __restrict__ x, const float* __restrict__ conv_w)
{
    extern __shared__ char smc[];
    const uint32_t sb = smem_u32(smc);
    const int tid  = threadIdx.x;
    const int w    = tid >> 5;
    const int lane = tid & 31;
    const int g    = lane >> 2;
    const int t4   = lane & 3;
    const int q    = lane >> 3;
    const int qi   = lane & 7;
    const int b    = blockIdx.x >> 3;
    const int s    = blockIdx.x & 7;

    const float* xb = x + (size_t)b * NV_C * NV_N + s * 512;

    // ---- W -> smem hi/lo (native [k][c], padded pitch) ----
    {
        int k = tid >> 2, c0 = (tid & 3) * 32;
        const float* wr = conv_w + k * NV_C + c0;
        char* wh = smc + W_HI + k * (PW * 2) + c0 * 2;
        char* wl = smc + W_LO + k * (PW * 2) + c0 * 2;
        #pragma unroll
        for (int e = 0; e < 8; e++) {
            float4 v = *(const float4*)(wr + 4 * e);
            __nv_bfloat16 h0 = __float2bfloat16(v.x), h1 = __float2bfloat16(v.y);
            __nv_bfloat16 h2 = __float2bfloat16(v.z), h3 = __float2bfloat16(v.w);
            float l0 = v.x - __bfloat162float(h0), l1 = v.y - __bfloat162float(h1);
            float l2 = v.z - __bfloat162float(h2), l3 = v.w - __bfloat162float(h3);
            *(__nv_bfloat162*)(wh + 8 * e)     = __nv_bfloat162(h0, h1);
            *(__nv_bfloat162*)(wh + 8 * e + 4) = __nv_bfloat162(h2, h3);
            *(__nv_bfloat162*)(wl + 8 * e)     = __nv_bfloat162(__float2bfloat16(l0), __float2bfloat16(l1));
            *(__nv_bfloat162*)(wl + 8 * e + 4) = __nv_bfloat162(__float2bfloat16(l2), __float2bfloat16(l3));
        }
    }

    // ---- warp role parameters ----
    const int nb  = w & 1;        // GEMM1: n-block (rows 32nb..32nb+31)
    const int kh  = (w >> 1) & 1; // GEMM1: k-half (k 32kh..32kh+31)
    const int cb  = (w & 3) * 32; // GEMM2: c-block
    const int kh2 = w >> 2;       // GEMM2: k-half

    // ---- per-lane ldmatrix base addresses ----
    // GEMM1 A (trans on Xn): smem row = c = cs*16 + (q>>1)*8 + qi,
    //                        col n = 32nb + 16i + (q&1)*8
    const uint32_t a1b = sb + XN_HI + (uint32_t)(((q >> 1) * 8 + qi) * (PX * 2))
                       + (uint32_t)((32 * nb + (q & 1) * 8) * 2);
    // GEMM1 B (W hi/lo via quadrant): row k = kt*8 + qi, col c = cs*16 + (q&1)*8
    const uint32_t b1b = sb + ((q & 2) ? W_LO : W_HI)
                       + (uint32_t)(qi * (PW * 2)) + (uint32_t)((q & 1) * 16);
    // GEMM2 A (Xn non-trans): row c = cb + 16i + (q&1)*8 + qi, col n = ns*16 + (q>>1)*8
    const uint32_t a2b = sb + XN_HI + (uint32_t)((cb + (q & 1) * 8 + qi) * (PX * 2))
                       + (uint32_t)(((q >> 1) * 8) * 2);
    // GEMM2 B (At trans, hi/lo via quadrant): row n = ns*16 + (q&1)*8 + qi,
    //                                         col k byte = 64*kh2 + 16*kt3
    const uint32_t b2b = sb + ((q & 2) ? AT_LO : AT_HI)
                       + (uint32_t)(((q & 1) * 8 + qi) * (PA * 2)) + (uint32_t)(kh2 * 64);

    float d2[2][4][4];
    float asum[4][2];
    #pragma unroll
    for (int i = 0; i < 2; i++)
        #pragma unroll
        for (int kt = 0; kt < 4; kt++)
            d2[i][kt][0] = d2[i][kt][1] = d2[i][kt][2] = d2[i][kt][3] = 0.f;
    #pragma unroll
    for (int kt = 0; kt < 4; kt++) asum[kt][0] = asum[kt][1] = 0.f;

    // conv addressing: c = tid>>1, n-half = (tid&1)*32
    const int cc = tid >> 1, nh = (tid & 1) * 32;
    const float* xrow = xb + (size_t)cc * NV_N + nh;
    char* const xh_base = smc + XN_HI + cc * (PX * 2) + nh * 2;
    char* const xl_base = smc + XN_LO + cc * (PX * 2) + nh * 2;

    float2* const stats = (float2*)(smc + AUX_B);   // [kh][64 rows] = (max, sum)

    for (int tt = 0; tt < NV_TILES; tt++) {
        __syncthreads();   // previous GEMM2 done reading Xn/At

        // ---- convert x tile -> Xn hi/lo [c][n=64] ----
        {
            const float* xr = xrow + tt * 64;
            #pragma unroll
            for (int j = 0; j < 8; j++) {
                float4 v = *(const float4*)(xr + 4 * j);
                __nv_bfloat16 h0 = __float2bfloat16(v.x), h1 = __float2bfloat16(v.y);
                __nv_bfloat16 h2 = __float2bfloat16(v.z), h3 = __float2bfloat16(v.w);
                float l0 = v.x - __bfloat162float(h0), l1 = v.y - __bfloat162float(h1);
                float l2 = v.z - __bfloat162float(h2), l3 = v.w - __bfloat162float(h3);
                *(__nv_bfloat162*)(xh_base + 8 * j)     = __nv_bfloat162(h0, h1);
                *(__nv_bfloat162*)(xh_base + 8 * j + 4) = __nv_bfloat162(h2, h3);
                *(__nv_bfloat162*)(xl_base + 8 * j)     = __nv_bfloat162(__float2bfloat16(l0), __float2bfloat16(l1));
                *(__nv_bfloat162*)(xl_base + 8 * j + 4) = __nv_bfloat162(__float2bfloat16(l2), __float2bfloat16(l3));
            }
        }
        __syncthreads();   // Xn ready

        // ---- GEMM1 (warps 0-3): L[32 n-rows][k-half] = Xt @ W^T, 3-term ----
        float d1[2][4][4];
        float m[2][2], sv[2][2], f[2][2];
        if (w < 4) {
            #pragma unroll
            for (int i = 0; i < 2; i++)
                #pragma unroll
                for (int kt = 0; kt < 4; kt++)
                    d1[i][kt][0] = d1[i][kt][1] = d1[i][kt][2] = d1[i][kt][3] = 0.f;

            #pragma unroll
            for (int cs = 0; cs < 8; cs++) {
                uint32_t ah[2][4], al[2][4];
                const uint32_t abase = a1b + cs * 16 * (PX * 2);
                ldmx4t(ah[0], abase);
                ldmx4t(al[0], abase + (XN_LO - XN_HI));
                ldmx4t(ah[1], abase + 32);
                ldmx4t(al[1], abase + 32 + (XN_LO - XN_HI));
                #pragma unroll
                for (int kt = 0; kt < 4; kt++) {
                    uint32_t bb[4];
                    ldmx4(bb, b1b + (4 * kh + kt) * (8 * PW * 2) + cs * 32);
                    #pragma unroll
                    for (int i = 0; i < 2; i++) {
                        mma16816(d1[i][kt], ah[i], bb);
                        mma16816(d1[i][kt], ah[i], bb + 2);
                        mma16816(d1[i][kt], al[i], bb);
                    }
                }
            }

            // local softmax stats over this warp's k-half
            #pragma unroll
            for (int i = 0; i < 2; i++) { m[i][0] = -1e30f; m[i][1] = -1e30f; }
            #pragma unroll
            for (int i = 0; i < 2; i++)
                #pragma unroll
                for (int kt = 0; kt < 4; kt++) {
                    m[i][0] = fmaxf(m[i][0], fmaxf(d1[i][kt][0], d1[i][kt][1]));
                    m[i][1] = fmaxf(m[i][1], fmaxf(d1[i][kt][2], d1[i][kt][3]));
                }
            #pragma unroll
            for (int i = 0; i < 2; i++)
                #pragma unroll
                for (int j = 0; j < 2; j++) {
                    m[i][j] = fmaxf(m[i][j], __shfl_xor_sync(0xffffffffu, m[i][j], 1));
                    m[i][j] = fmaxf(m[i][j], __shfl_xor_sync(0xffffffffu, m[i][j], 2));
                    sv[i][j] = 0.f;
                }
            #pragma unroll
            for (int i = 0; i < 2; i++)
                #pragma unroll
                for (int kt = 0; kt < 4; kt++) {
                    d1[i][kt][0] = __expf(d1[i][kt][0] - m[i][0]); sv[i][0] += d1[i][kt][0];
                    d1[i][kt][1] = __expf(d1[i][kt][1] - m[i][0]); sv[i][0] += d1[i][kt][1];
                    d1[i][kt][2] = __expf(d1[i][kt][2] - m[i][1]); sv[i][1] += d1[i][kt][2];
                    d1[i][kt][3] = __expf(d1[i][kt][3] - m[i][1]); sv[i][1] += d1[i][kt][3];
                }
            #pragma unroll
            for (int i = 0; i < 2; i++)
                #pragma unroll
                for (int j = 0; j < 2; j++) {
                    sv[i][j] += __shfl_xor_sync(0xffffffffu, sv[i][j], 1);
                    sv[i][j] += __shfl_xor_sync(0xffffffffu, sv[i][j], 2);
                }
            if (t4 == 0) {
                #pragma unroll
                for (int i = 0; i < 2; i++)
                    #pragma unroll
                    for (int j = 0; j < 2; j++)
                        stats[kh * 64 + 32 * nb + 16 * i + 8 * j + g] =
                            make_float2(m[i][j], sv[i][j]);
            }
        }
        __syncthreads();   // stats visible

        // ---- combine halves, write At hi/lo ----
        if (w < 4) {
            #pragma unroll
            for (int i = 0; i < 2; i++)
                #pragma unroll
                for (int j = 0; j < 2; j++) {
                    float2 r = stats[(kh ^ 1) * 64 + 32 * nb + 16 * i + 8 * j + g];
                    float M = fmaxf(m[i][j], r.x);
                    float S = sv[i][j] * __expf(m[i][j] - M) + r.y * __expf(r.x - M);
                    f[i][j] = __expf(m[i][j] - M) / S;
                }
            const uint32_t colb = (uint32_t)((32 * kh + 2 * t4) * 2);
            #pragma unroll
            for (int i = 0; i < 2; i++) {
                const int r0 = 32 * nb + 16 * i + g;
                char* p0 = smc + AT_HI + r0 * (PA * 2) + colb;
                char* p1 = p0 + 8 * (PA * 2);
                #pragma unroll
                for (int kt = 0; kt < 4; kt++) {
                    float a00 = d1[i][kt][0] * f[i][0], a01 = d1[i][kt][1] * f[i][0];
                    float a10 = d1[i][kt][2] * f[i][1], a11 = d1[i][kt][3] * f[i][1];
                    asum[kt][0] += a00 + a10;
                    asum[kt][1] += a01 + a11;
                    __nv_bfloat16 h00 = __float2bfloat16(a00), h01 = __float2bfloat16(a01);
                    __nv_bfloat16 h10 = __float2bfloat16(a10), h11 = __float2bfloat16(a11);
                    float e00 = a00 - __bfloat162float(h00), e01 = a01 - __bfloat162float(h01);
                    float e10 = a10 - __bfloat162float(h10), e11 = a11 - __bfloat162float(h11);
                    *(__nv_bfloat162*)(p0 + kt * 16) = __nv_bfloat162(h00, h01);
                    *(__nv_bfloat162*)(p1 + kt * 16) = __nv_bfloat162(h10, h11);
                    *(__nv_bfloat162*)(p0 + kt * 16 + (AT_LO - AT_HI)) =
                        __nv_bfloat162(__float2bfloat16(e00), __float2bfloat16(e01));
                    *(__nv_bfloat162*)(p1 + kt * 16 + (AT_LO - AT_HI)) =
                        __nv_bfloat162(__float2bfloat16(e10), __float2bfloat16(e11));
                }
            }
        }
        __syncthreads();   // At ready

        // ---- GEMM2 (all 8 warps): V[32 c-rows][k-half] += Xn @ At^T ----
        #pragma unroll
        for (int ns = 0; ns < 4; ns++) {
            uint32_t ah[2][4], al[2][4];
            const uint32_t abase = a2b + ns * 32;
            ldmx4(ah[0], abase);
            ldmx4(al[0], abase + (XN_LO - XN_HI));
            ldmx4(ah[1], abase + 16 * (PX * 2));
            ldmx4(al[1], abase + 16 * (PX * 2) + (XN_LO - XN_HI));
            #pragma unroll
            for (int kt = 0; kt < 4; kt++) {
                uint32_t bb[4];
                ldmx4t(bb, b2b + ns * 16 * (PA * 2) + kt * 16);
                #pragma unroll
                for (int i = 0; i < 2; i++) {
                    mma16816(d2[i][kt], ah[i], bb);
                    mma16816(d2[i][kt], ah[i], bb + 2);
                    mma16816(d2[i][kt], al[i], bb);
                }
            }
        }
    }

    __syncthreads();

    // ---- stage D2 into XN region as [k][c] fp32, coalesced drain ----
    {
        float* dstg = (float*)(smc + XN_HI);
        #pragma unroll
        for (int i = 0; i < 2; i++) {
            const int cr = cb + 16 * i + g;
            #pragma unroll
            for (int kt = 0; kt < 4; kt++) {
                const int K0 = 32 * kh2 + 8 * kt + 2 * t4;
                dstg[K0 * NV_C + cr]           = d2[i][kt][0];
                dstg[(K0 + 1) * NV_C + cr]     = d2[i][kt][1];
                dstg[K0 * NV_C + cr + 8]       = d2[i][kt][2];
                dstg[(K0 + 1) * NV_C + cr + 8] = d2[i][kt][3];
            }
        }
        __syncthreads();
        float4* pv4 = (float4*)(g_pvlad + (size_t)blockIdx.x * (NV_K * NV_C));
        const float4* sg4 = (const float4*)dstg;
        #pragma unroll
        for (int i = 0; i < 8; i++)
            pv4[i * 256 + tid] = sg4[i * 256 + tid];
    }

    // ---- asum reduce (warps 0-3 carry sums for their k-half) ----
    float* asum_buf = (float*)(smc + AUX_B);
    if (w < 4) {
        #pragma unroll
        for (int kt = 0; kt < 4; kt++)
            #pragma unroll
            for (int j = 0; j < 2; j++) {
                float vv = asum[kt][j];
                vv += __shfl_xor_sync(0xffffffffu, vv, 4);
                vv += __shfl_xor_sync(0xffffffffu, vv, 8);
                vv += __shfl_xor_sync(0xffffffffu, vv, 16);
                asum[kt][j] = vv;
            }
        if (lane < 4) {
            #pragma unroll
            for (int kt = 0; kt < 4; kt++) {
                asum_buf[w * 32 + kt * 8 + 2 * t4]     = asum[kt][0];
                asum_buf[w * 32 + kt * 8 + 2 * t4 + 1] = asum[kt][1];
            }
        }
    }
    __syncthreads();
    if (tid < 64) {
        // k = 32*khv + kl ; k-half khv covered by warps (2*khv) and (2*khv+1)
        const int khv = tid >> 5, kl = tid & 31;
        g_pasum[blockIdx.x * NV_K + tid] =
            asum_buf[(2 * khv) * 32 + kl] + asum_buf[(2 * khv + 1) * 32 + kl];
    }
}

// ---------------------------------------------------------------------------
// finalize: reduce splits, subtract asum*centroid, intra + global L2 normalize
// ---------------------------------------------------------------------------
__global__ __launch_bounds__(1024)
void netvlad_finalize(const float* __restrict__ centroids, float* __restrict__ out)
{
    __shared__ float vbuf[NV_K * NV_C];
    __shared__ float wpart[NV_K][4];
    __shared__ float asumt[NV_K];
    __shared__ float invrow[NV_K];
    __shared__ float g2[2];

    const int b = blockIdx.x, t = threadIdx.x;
    const int w = t >> 5, lane = t & 31;

    if (t < NV_K) {
        float sum = 0.f;
        #pragma unroll
        for (int sp = 0; sp < NV_SPLIT; sp++)
            sum += g_pasum[(b * NV_SPLIT + sp) * NV_K + t];
        asumt[t] = sum;
    }
    __syncthreads();

    const size_t base = (size_t)b * NV_SPLIT * (NV_K * NV_C);
    #pragma unroll
    for (int i = 0; i < 8; i++) {
        int flat = i * 1024 + t;
        int k = flat >> 7;
        float v = 0.f;
        #pragma unroll
        for (int sp = 0; sp < NV_SPLIT; sp++)
            v += g_pvlad[base + (size_t)sp * (NV_K * NV_C) + flat];
        v -= asumt[k] * centroids[flat];
        vbuf[flat] = v;
        float v2 = v * v;
        #pragma unroll
        for (int o = 16; o > 0; o >>= 1)
            v2 += __shfl_xor_sync(0xffffffffu, v2, o);
        if (lane == 0) wpart[k][w & 3] = v2;
    }
    __syncthreads();

    if (t < NV_K) {
        float rs  = wpart[t][0] + wpart[t][1] + wpart[t][2] + wpart[t][3];
        float rn  = sqrtf(rs);
        float inv = 1.0f / fmaxf(rn, 1e-12f);
        invrow[t] = inv;
        float c1 = rn * inv;
        float contrib = c1 * c1;
        #pragma unroll
        for (int o = 16; o > 0; o >>= 1)
            contrib += __shfl_xor_sync(0xffffffffu, contrib, o);
        if (lane == 0) g2[w] = contrib;
    }
    __syncthreads();

    const float ginv = 1.0f / fmaxf(sqrtf(g2[0] + g2[1]), 1e-12f);
    float* ob = out + (size_t)b * (NV_K * NV_C);
    #pragma unroll
    for (int i = 0; i < 8; i++) {
        int flat = i * 1024 + t;
        ob[flat] = vbuf[flat] * invrow[flat >> 7] * ginv;
    }
}

__global__ void netvlad_nop() {}

// ---------------------------------------------------------------------------
extern "C" void kernel_launch(void* const* d_in, const int* in_sizes, int n_in,
                              void* d_out, int out_size)
{
    const float* x         = (const float*)d_in[0];
    const float* conv_w    = (const float*)d_in[1];
    const float* centroids = (const float*)d_in[2];
    float* out = (float*)d_out;

    cudaFuncSetAttribute(netvlad_mma,
                         cudaFuncAttributeMaxDynamicSharedMemorySize, SMEM_TOTAL);
    // 3 launches: ncu -s 5 -c 1 with +2 hidden-launch offset captures netvlad_mma.
    netvlad_mma<<<NV_B * NV_SPLIT, 256, SMEM_TOTAL>>>(x, conv_w);
    netvlad_finalize<<<NV_B, 1024>>>(centroids, out);
    netvlad_nop<<<1, 32>>>();
}